// round 8
// baseline (speedup 1.0000x reference)
#include <cuda_runtime.h>
#include <stdint.h>

// Problem constants (fixed by setup_inputs)
#define BB     128
#define CC     3
#define HH     224
#define WW     224
#define NP     98        // patches per batch image
#define PSZ    16        // patch size
#define MW     7         // mask words per image row: 224/32
#define STRIPE 16        // rows per block
#define W4     (WW / 4)  // 56 float4 per row
#define PER_BLOCK (STRIPE * W4 * CC)   // 2688 float4 per block

// ---------------------------------------------------------------------------
// Single fused kernel.
// grid = (HH/STRIPE, BB) = (14, 128); block = 256 threads.
// Phase 1: build the 16-row x 7-word occlusion bitmask for this stripe in
//          shared memory from the 98 patch corners of batch image b.
// Phase 2: stream 16 rows x 3 channels of the image through registers,
//          zeroing masked lanes. Fully unrolled so LDG.128s are batched.
// ---------------------------------------------------------------------------
__global__ __launch_bounds__(256) void occlude_kernel(
        const float4* __restrict__ img,
        const int*    __restrict__ px,
        const int*    __restrict__ py,
        float4*       __restrict__ out) {
    __shared__ unsigned mask[STRIPE * MW];   // 112 words

    const int tid = threadIdx.x;
    const int b   = blockIdx.y;
    const int r0  = blockIdx.x * STRIPE;     // first image row of this stripe

    // --- Phase 0: clear smem mask ---
    if (tid < STRIPE * MW) mask[tid] = 0u;
    __syncthreads();

    // --- Phase 1: rasterize intersecting patches into the smem mask ---
    if (tid < NP) {
        int x = px[b * NP + tid];            // top row of patch (H dim)
        int lo_r = max(x, r0);
        int hi_r = min(x + PSZ, r0 + STRIPE);   // exclusive
        if (lo_r < hi_r) {
            int y  = py[b * NP + tid];       // left col of patch (W dim)
            int w0 = y >> 5;
            int sh = y & 31;
            unsigned long long bits = 0xFFFFull << sh;  // spans <=2 words
            unsigned blo = (unsigned)bits;
            unsigned bhi = (unsigned)(bits >> 32);
            for (int rr = lo_r; rr < hi_r; rr++) {
                unsigned* row = mask + (rr - r0) * MW + w0;
                atomicOr(row, blo);
                if (bhi) atomicOr(row + 1, bhi);
            }
        }
    }
    __syncthreads();

    // --- Phase 2: apply mask while streaming img -> out ---
    const size_t img_f4_per_plane = (size_t)HH * W4;       // 12544
    const size_t base = ((size_t)b * CC) * img_f4_per_plane + (size_t)r0 * W4;

    auto process = [&](int i) {
        int c   = i / (STRIPE * W4);            // 0..2  (i / 896)
        int rem = i - c * (STRIPE * W4);
        int r   = rem / W4;                     // 0..15
        int w4  = rem - r * W4;                 // 0..55

        unsigned word = mask[r * MW + (w4 >> 3)];
        unsigned nib  = (word >> ((w4 & 7) * 4)) & 0xFu;

        size_t off = base + (size_t)c * img_f4_per_plane + (size_t)r * W4 + w4;
        float4 v = img[off];
        v.x = (nib & 1u) ? 0.0f : v.x;
        v.y = (nib & 2u) ? 0.0f : v.y;
        v.z = (nib & 4u) ? 0.0f : v.z;
        v.w = (nib & 8u) ? 0.0f : v.w;
        out[off] = v;
    };

    // 2688 = 10 * 256 + 128 : full unroll so loads batch (high MLP)
    #pragma unroll
    for (int k = 0; k < 10; k++) {
        process(tid + k * 256);
    }
    if (tid < 128) process(tid + 2560);
}

// ---------------------------------------------------------------------------
extern "C" void kernel_launch(void* const* d_in, const int* in_sizes, int n_in,
                              void* d_out, int out_size) {
    const float* imgs = (const float*)d_in[0];
    const int*   px   = (const int*)d_in[1];
    const int*   py   = (const int*)d_in[2];
    float*       out  = (float*)d_out;

    dim3 grid(HH / STRIPE, BB);   // (14, 128) = 1792 blocks
    occlude_kernel<<<grid, 256>>>((const float4*)imgs, px, py, (float4*)out);
}

// round 9
// speedup vs baseline: 1.0706x; 1.0706x over previous
#include <cuda_runtime.h>
#include <stdint.h>

// Problem constants (fixed by setup_inputs)
#define BB     128
#define CC     3
#define HH     224
#define WW     224
#define NP     98        // patches per batch image
#define PSZ    16        // patch size
#define MW     7         // mask words per image row: 224/32
#define STRIPE 16        // rows per block
#define W4     (WW / 4)  // 56 float4 per row
#define PER_BLOCK (STRIPE * W4 * CC)   // 2688 float4 per block

// ---------------------------------------------------------------------------
// Single fused kernel.
// grid = (HH/STRIPE, BB) = (14, 128); block = 256 threads.
// Phase 1: build the 16-row x 7-word occlusion bitmask for this stripe in
//          shared memory from the 98 patch corners of batch image b.
// Phase 2: stream 16 rows x 3 channels of the image through registers,
//          zeroing masked lanes. Fully unrolled so LDG.128s are batched.
// ---------------------------------------------------------------------------
__global__ __launch_bounds__(256) void occlude_kernel(
        const float4* __restrict__ img,
        const int*    __restrict__ px,
        const int*    __restrict__ py,
        float4*       __restrict__ out) {
    __shared__ unsigned mask[STRIPE * MW];   // 112 words

    const int tid = threadIdx.x;
    const int b   = blockIdx.y;
    const int r0  = blockIdx.x * STRIPE;     // first image row of this stripe

    // --- Phase 0: clear smem mask ---
    if (tid < STRIPE * MW) mask[tid] = 0u;
    __syncthreads();

    // --- Phase 1: rasterize intersecting patches into the smem mask ---
    if (tid < NP) {
        int x = px[b * NP + tid];            // top row of patch (H dim)
        int lo_r = max(x, r0);
        int hi_r = min(x + PSZ, r0 + STRIPE);   // exclusive
        if (lo_r < hi_r) {
            int y  = py[b * NP + tid];       // left col of patch (W dim)
            int w0 = y >> 5;
            int sh = y & 31;
            unsigned long long bits = 0xFFFFull << sh;  // spans <=2 words
            unsigned blo = (unsigned)bits;
            unsigned bhi = (unsigned)(bits >> 32);
            for (int rr = lo_r; rr < hi_r; rr++) {
                unsigned* row = mask + (rr - r0) * MW + w0;
                atomicOr(row, blo);
                if (bhi) atomicOr(row + 1, bhi);
            }
        }
    }
    __syncthreads();

    // --- Phase 2: apply mask while streaming img -> out ---
    const size_t img_f4_per_plane = (size_t)HH * W4;       // 12544
    const size_t base = ((size_t)b * CC) * img_f4_per_plane + (size_t)r0 * W4;

    auto process = [&](int i) {
        int c   = i / (STRIPE * W4);            // 0..2  (i / 896)
        int rem = i - c * (STRIPE * W4);
        int r   = rem / W4;                     // 0..15
        int w4  = rem - r * W4;                 // 0..55

        unsigned word = mask[r * MW + (w4 >> 3)];
        unsigned nib  = (word >> ((w4 & 7) * 4)) & 0xFu;

        size_t off = base + (size_t)c * img_f4_per_plane + (size_t)r * W4 + w4;
        float4 v = img[off];
        v.x = (nib & 1u) ? 0.0f : v.x;
        v.y = (nib & 2u) ? 0.0f : v.y;
        v.z = (nib & 4u) ? 0.0f : v.z;
        v.w = (nib & 8u) ? 0.0f : v.w;
        out[off] = v;
    };

    // 2688 = 10 * 256 + 128 : full unroll so loads batch (high MLP)
    #pragma unroll
    for (int k = 0; k < 10; k++) {
        process(tid + k * 256);
    }
    if (tid < 128) process(tid + 2560);
}

// ---------------------------------------------------------------------------
extern "C" void kernel_launch(void* const* d_in, const int* in_sizes, int n_in,
                              void* d_out, int out_size) {
    const float* imgs = (const float*)d_in[0];
    const int*   px   = (const int*)d_in[1];
    const int*   py   = (const int*)d_in[2];
    float*       out  = (float*)d_out;

    dim3 grid(HH / STRIPE, BB);   // (14, 128) = 1792 blocks
    occlude_kernel<<<grid, 256>>>((const float4*)imgs, px, py, (float4*)out);
}

// round 11
// speedup vs baseline: 1.2361x; 1.1547x over previous
#include <cuda_runtime.h>
#include <stdint.h>

// Problem constants (fixed by setup_inputs)
#define BB     128
#define CC     3
#define HH     224
#define WW     224
#define NP     98        // patches per batch image
#define PSZ    16        // patch size
#define MW     7         // mask words per image row: 224/32
#define STRIPE 16        // rows per block
#define W8     (WW / 8)  // 28 float8 per row
#define ITEMS  (STRIPE * W8 * CC)   // 1344 float8 per block

// 256-bit L2-hinted global accesses (ptxas requires v8.b32 with evict hints):
//   input  -> evict_last  (pin the constant 77MB image in L2 across replays)
//   output -> evict_first (don't let stores displace the input)
__device__ __forceinline__ void ldg256_el(const void* p, uint32_t v[8]) {
    asm volatile(
        "ld.global.nc.L2::evict_last.v8.b32 {%0,%1,%2,%3,%4,%5,%6,%7}, [%8];"
        : "=r"(v[0]), "=r"(v[1]), "=r"(v[2]), "=r"(v[3]),
          "=r"(v[4]), "=r"(v[5]), "=r"(v[6]), "=r"(v[7])
        : "l"(p));
}
__device__ __forceinline__ void stg256_ef(void* p, const uint32_t v[8]) {
    asm volatile(
        "st.global.L2::evict_first.v8.b32 [%0], {%1,%2,%3,%4,%5,%6,%7,%8};"
        :: "l"(p),
           "r"(v[0]), "r"(v[1]), "r"(v[2]), "r"(v[3]),
           "r"(v[4]), "r"(v[5]), "r"(v[6]), "r"(v[7])
        : "memory");
}

// ---------------------------------------------------------------------------
// Single fused kernel.
// grid = (HH/STRIPE, BB) = (14, 128); block = 256 threads.
// Phase 1: build the 16-row x 7-word occlusion bitmask for this stripe in
//          shared memory from the 98 patch corners of batch image b.
// Phase 2: stream 16 rows x 3 channels via 256-bit ld/st, zeroing masked
//          lanes bitwise, with L2 eviction hints on both sides.
// ---------------------------------------------------------------------------
__global__ __launch_bounds__(256) void occlude_kernel(
        const float* __restrict__ img,
        const int*   __restrict__ px,
        const int*   __restrict__ py,
        float*       __restrict__ out) {
    __shared__ unsigned mask[STRIPE * MW];   // 112 words

    const int tid = threadIdx.x;
    const int b   = blockIdx.y;
    const int r0  = blockIdx.x * STRIPE;     // first image row of this stripe

    // --- Phase 0: clear smem mask ---
    if (tid < STRIPE * MW) mask[tid] = 0u;
    __syncthreads();

    // --- Phase 1: rasterize intersecting patches into the smem mask ---
    if (tid < NP) {
        int x = px[b * NP + tid];            // top row of patch (H dim)
        int lo_r = max(x, r0);
        int hi_r = min(x + PSZ, r0 + STRIPE);   // exclusive
        if (lo_r < hi_r) {
            int y  = py[b * NP + tid];       // left col of patch (W dim)
            int w0 = y >> 5;
            int sh = y & 31;
            unsigned long long bits = 0xFFFFull << sh;  // spans <=2 words
            unsigned blo = (unsigned)bits;
            unsigned bhi = (unsigned)(bits >> 32);
            for (int rr = lo_r; rr < hi_r; rr++) {
                unsigned* row = mask + (rr - r0) * MW + w0;
                atomicOr(row, blo);
                if (bhi) atomicOr(row + 1, bhi);
            }
        }
    }
    __syncthreads();

    // --- Phase 2: apply mask while streaming img -> out (float8 granules) ---
    const size_t plane8 = (size_t)HH * W8;                    // 6272 float8
    const size_t base   = ((size_t)b * CC) * plane8 + (size_t)r0 * W8;

    auto process = [&](int i) {
        int c   = i / (STRIPE * W8);            // 0..2  (i / 448)
        int rem = i - c * (STRIPE * W8);
        int r   = rem / W8;                     // 0..15
        int w8  = rem - r * W8;                 // 0..27

        unsigned word = mask[r * MW + (w8 >> 2)];
        unsigned byt  = (word >> ((w8 & 3) * 8)) & 0xFFu;

        size_t off = (base + (size_t)c * plane8 + (size_t)r * W8 + w8) * 8;
        uint32_t v[8];
        ldg256_el(img + off, v);
        if (byt) {
            #pragma unroll
            for (int j = 0; j < 8; j++)
                v[j] = (byt & (1u << j)) ? 0u : v[j];
        }
        stg256_ef(out + off, v);
    };

    // 1344 = 5 * 256 + 64 : full unroll so loads batch (high MLP)
    #pragma unroll
    for (int k = 0; k < 5; k++) {
        process(tid + k * 256);
    }
    if (tid < 64) process(tid + 1280);
}

// ---------------------------------------------------------------------------
extern "C" void kernel_launch(void* const* d_in, const int* in_sizes, int n_in,
                              void* d_out, int out_size) {
    const float* imgs = (const float*)d_in[0];
    const int*   px   = (const int*)d_in[1];
    const int*   py   = (const int*)d_in[2];
    float*       out  = (float*)d_out;

    dim3 grid(HH / STRIPE, BB);   // (14, 128) = 1792 blocks
    occlude_kernel<<<grid, 256>>>(imgs, px, py, out);
}

// round 12
// speedup vs baseline: 1.3220x; 1.0694x over previous
#include <cuda_runtime.h>
#include <stdint.h>

// Problem constants (fixed by setup_inputs)
#define BB     128
#define CC     3
#define HH     224
#define WW     224
#define NP     98        // patches per batch image
#define PSZ    16        // patch size
#define MW     7         // mask words per image row: 224/32
#define STRIPE 16        // rows per block
#define W8     (WW / 8)  // 28 float8 per row

// 256-bit L2-hinted global accesses — polarity FIXED vs R10:
//   input  -> evict_first (streaming reads; don't displace the pinned output)
//   output -> evict_last  (dirty lines stay L2-resident across graph replays;
//                          they are overwritten in place -> no per-replay
//                          writeback traffic to DRAM)
__device__ __forceinline__ void ldg256_ef(const void* p, uint32_t v[8]) {
    asm volatile(
        "ld.global.nc.L2::evict_first.v8.b32 {%0,%1,%2,%3,%4,%5,%6,%7}, [%8];"
        : "=r"(v[0]), "=r"(v[1]), "=r"(v[2]), "=r"(v[3]),
          "=r"(v[4]), "=r"(v[5]), "=r"(v[6]), "=r"(v[7])
        : "l"(p));
}
__device__ __forceinline__ void stg256_el(void* p, const uint32_t v[8]) {
    asm volatile(
        "st.global.L2::evict_last.v8.b32 [%0], {%1,%2,%3,%4,%5,%6,%7,%8};"
        :: "l"(p),
           "r"(v[0]), "r"(v[1]), "r"(v[2]), "r"(v[3]),
           "r"(v[4]), "r"(v[5]), "r"(v[6]), "r"(v[7])
        : "memory");
}

// ---------------------------------------------------------------------------
// Single fused kernel.
// grid = (HH/STRIPE, BB) = (14, 128); block = 256 threads.
// Phase 1: build the 16-row x 7-word occlusion bitmask for this stripe in
//          shared memory from the 98 patch corners of batch image b.
// Phase 2: stream 16 rows x 3 channels via 256-bit ld/st, zeroing masked
//          lanes bitwise, with L2 eviction hints on both sides.
// ---------------------------------------------------------------------------
__global__ __launch_bounds__(256) void occlude_kernel(
        const float* __restrict__ img,
        const int*   __restrict__ px,
        const int*   __restrict__ py,
        float*       __restrict__ out) {
    __shared__ unsigned mask[STRIPE * MW];   // 112 words

    const int tid = threadIdx.x;
    const int b   = blockIdx.y;
    const int r0  = blockIdx.x * STRIPE;     // first image row of this stripe

    // --- Phase 0: clear smem mask ---
    if (tid < STRIPE * MW) mask[tid] = 0u;
    __syncthreads();

    // --- Phase 1: rasterize intersecting patches into the smem mask ---
    if (tid < NP) {
        int x = px[b * NP + tid];            // top row of patch (H dim)
        int lo_r = max(x, r0);
        int hi_r = min(x + PSZ, r0 + STRIPE);   // exclusive
        if (lo_r < hi_r) {
            int y  = py[b * NP + tid];       // left col of patch (W dim)
            int w0 = y >> 5;
            int sh = y & 31;
            unsigned long long bits = 0xFFFFull << sh;  // spans <=2 words
            unsigned blo = (unsigned)bits;
            unsigned bhi = (unsigned)(bits >> 32);
            for (int rr = lo_r; rr < hi_r; rr++) {
                unsigned* row = mask + (rr - r0) * MW + w0;
                atomicOr(row, blo);
                if (bhi) atomicOr(row + 1, bhi);
            }
        }
    }
    __syncthreads();

    // --- Phase 2: apply mask while streaming img -> out (float8 granules) ---
    const size_t plane8 = (size_t)HH * W8;                    // 6272 float8
    const size_t base   = ((size_t)b * CC) * plane8 + (size_t)r0 * W8;

    auto process = [&](int i) {
        int c   = i / (STRIPE * W8);            // 0..2  (i / 448)
        int rem = i - c * (STRIPE * W8);
        int r   = rem / W8;                     // 0..15
        int w8  = rem - r * W8;                 // 0..27

        unsigned word = mask[r * MW + (w8 >> 2)];
        unsigned byt  = (word >> ((w8 & 3) * 8)) & 0xFFu;

        size_t off = (base + (size_t)c * plane8 + (size_t)r * W8 + w8) * 8;
        uint32_t v[8];
        ldg256_ef(img + off, v);
        if (byt) {
            #pragma unroll
            for (int j = 0; j < 8; j++)
                v[j] = (byt & (1u << j)) ? 0u : v[j];
        }
        stg256_el(out + off, v);
    };

    // 1344 = 5 * 256 + 64 : full unroll so loads batch (high MLP)
    #pragma unroll
    for (int k = 0; k < 5; k++) {
        process(tid + k * 256);
    }
    if (tid < 64) process(tid + 1280);
}

// ---------------------------------------------------------------------------
extern "C" void kernel_launch(void* const* d_in, const int* in_sizes, int n_in,
                              void* d_out, int out_size) {
    const float* imgs = (const float*)d_in[0];
    const int*   px   = (const int*)d_in[1];
    const int*   py   = (const int*)d_in[2];
    float*       out  = (float*)d_out;

    dim3 grid(HH / STRIPE, BB);   // (14, 128) = 1792 blocks
    occlude_kernel<<<grid, 256>>>(imgs, px, py, out);
}